// round 1
// baseline (speedup 1.0000x reference)
#include <cuda_runtime.h>
#include <math.h>

#define HDIM   128
#define NMAX   100000
#define EMAX   1000000
#define CDIM   16
#define FDIM   288   // 2*HDIM + 32

// Scratch (static device globals — allocation-free per harness rules)
__device__ float g_dinv[NMAX];
__device__ float g_h  [(size_t)NMAX * HDIM];
__device__ float g_lin[(size_t)NMAX * HDIM];
__device__ float g_agg[(size_t)NMAX * HDIM];

// ---------------------------------------------------------------- degree
__global__ void k_deg_init(int n) {
    int i = blockIdx.x * blockDim.x + threadIdx.x;
    if (i < n) g_dinv[i] = 1.0f;           // deg starts at 1 (self-loop)
}
__global__ void k_deg_count(const int* __restrict__ dst, int e) {
    int i = blockIdx.x * blockDim.x + threadIdx.x;
    if (i < e) atomicAdd(&g_dinv[dst[i]], 1.0f);
}
__global__ void k_deg_rsqrt(int n) {
    int i = blockIdx.x * blockDim.x + threadIdx.x;
    if (i < n) g_dinv[i] = rsqrtf(g_dinv[i]);
}

// ---------------------------------------------------------------- zero agg
__global__ void k_zero(int n4) {
    int i = blockIdx.x * blockDim.x + threadIdx.x;
    if (i < n4) ((float4*)g_agg)[i] = make_float4(0.f, 0.f, 0.f, 0.f);
}

// ---------------------------------------------------------------- GEMM: out = A @ W   (A: M x 128, W: 128 x 128)
// A == nullptr means "read g_h". Writes g_lin.
// Block: 256 threads (8 warps), BM=64 rows. W fully smem-resident.
// Each warp: 8 rows; each lane: 4 cols => 8x4 register micro-tile.
#define GEMM_BM 64
#define GEMM_SMEM ((128*128 + GEMM_BM*128) * 4)
__global__ void k_gemm128(const float* __restrict__ Aext,
                          const float* __restrict__ W, int M) {
    extern __shared__ float sm[];
    float*  Ws  = sm;                 // 128*128
    float*  As  = sm + 128 * 128;     // BM*128
    float4* Ws4 = (float4*)Ws;
    float4* As4 = (float4*)As;

    const float* A = Aext ? Aext : g_h;
    int tid = threadIdx.x;

    // load W (4096 float4, 16 per thread)
    const float4* W4 = (const float4*)W;
    #pragma unroll
    for (int i = 0; i < 16; i++) Ws4[tid + i * 256] = W4[tid + i * 256];

    // load A tile (BM*32 = 2048 float4, 8 per thread), zero-pad OOB rows
    int row0 = blockIdx.x * GEMM_BM;
    const float4* A4 = (const float4*)A;
    #pragma unroll
    for (int i = 0; i < 8; i++) {
        int idx = tid + i * 256;       // 0..2047
        int r   = idx >> 5;
        As4[idx] = (row0 + r < M) ? A4[(size_t)(row0 + r) * 32 + (idx & 31)]
                                  : make_float4(0.f, 0.f, 0.f, 0.f);
    }
    __syncthreads();

    int warp = tid >> 5, lane = tid & 31;
    int rbase = warp * 8;

    float4 acc[8];
    #pragma unroll
    for (int r = 0; r < 8; r++) acc[r] = make_float4(0.f, 0.f, 0.f, 0.f);

    #pragma unroll 8
    for (int k = 0; k < 128; k++) {
        float4 w = Ws4[k * 32 + lane];
        #pragma unroll
        for (int r = 0; r < 8; r++) {
            float a = As[(rbase + r) * 128 + k];
            acc[r].x += a * w.x; acc[r].y += a * w.y;
            acc[r].z += a * w.z; acc[r].w += a * w.w;
        }
    }

    float4* O4 = (float4*)g_lin;
    #pragma unroll
    for (int r = 0; r < 8; r++) {
        int row = row0 + rbase + r;
        if (row < M) O4[(size_t)row * 32 + lane] = acc[r];
    }
}

// ---------------------------------------------------------------- scatter: agg[dst] += lin[src] * dinv[src]*dinv[dst]
// One warp per edge; each lane owns one float4 (4 cols).
__global__ void k_scatter(const int* __restrict__ src, const int* __restrict__ dst, int e) {
    int g    = blockIdx.x * blockDim.x + threadIdx.x;
    int edge = g >> 5;
    int lane = g & 31;
    if (edge >= e) return;
    int s = src[edge], d = dst[edge];
    float norm = g_dinv[s] * g_dinv[d];
    float4 v = ((const float4*)(g_lin + (size_t)s * HDIM))[lane];
    float* ad = g_agg + (size_t)d * HDIM + lane * 4;
    atomicAdd(ad + 0, v.x * norm);
    atomicAdd(ad + 1, v.y * norm);
    atomicAdd(ad + 2, v.z * norm);
    atomicAdd(ad + 3, v.w * norm);
}

// ---------------------------------------------------------------- finalize: h = relu(agg + lin*dinv^2 + b)
__global__ void k_finalize(const float* __restrict__ b, int n) {
    int idx = blockIdx.x * blockDim.x + threadIdx.x;  // over n*32 float4
    if (idx >= n * 32) return;
    int row = idx >> 5, c4 = idx & 31;
    float di = g_dinv[row];
    float sl = di * di;
    float4 l  = ((const float4*)g_lin)[idx];
    float4 a  = ((const float4*)g_agg)[idx];
    float4 bb = ((const float4*)b)[c4];
    float4 o;
    o.x = fmaxf(fmaf(l.x, sl, a.x) + bb.x, 0.f);
    o.y = fmaxf(fmaf(l.y, sl, a.y) + bb.y, 0.f);
    o.z = fmaxf(fmaf(l.z, sl, a.z) + bb.z, 0.f);
    o.w = fmaxf(fmaf(l.w, sl, a.w) + bb.w, 0.f);
    ((float4*)g_h)[idx] = o;
}

// ---------------------------------------------------------------- edge classifier + log_softmax
// One warp per edge. Feature vector (288) staged in smem; lanes c and c+16
// split the K range for class c, shuffle-combined; warp-shuffle softmax.
__global__ void k_edge(const int* __restrict__ src, const int* __restrict__ dst,
                       const float* __restrict__ eattr,
                       const float* __restrict__ Wfc, const float* __restrict__ bfc,
                       float* __restrict__ out, int e) {
    __shared__ float Ws[FDIM * CDIM];   // 18 KB
    __shared__ float bs[CDIM];
    __shared__ float feat[8][FDIM];

    int tid = threadIdx.x;
    for (int i = tid; i < FDIM * CDIM; i += 256) Ws[i] = Wfc[i];
    if (tid < CDIM) bs[tid] = bfc[tid];
    __syncthreads();

    int warp = tid >> 5, lane = tid & 31;
    int edge = blockIdx.x * 8 + warp;
    if (edge >= e) return;

    int s = src[edge], d = dst[edge];
    float4* f4 = (float4*)feat[warp];
    f4[lane]      = ((const float4*)(g_h + (size_t)s * HDIM))[lane];
    f4[32 + lane] = ((const float4*)(g_h + (size_t)d * HDIM))[lane];
    if (lane < 8)
        f4[64 + lane] = ((const float4*)(eattr + (size_t)edge * 32))[lane];
    __syncwarp();

    int c    = lane & 15;
    int half = lane >> 4;           // split K: 144 each
    const float* fw = feat[warp];
    float acc = 0.f;
    int k0 = half * 144;
    #pragma unroll 8
    for (int k = k0; k < k0 + 144; k++)
        acc = fmaf(fw[k], Ws[k * CDIM + c], acc);
    acc += __shfl_xor_sync(0xffffffffu, acc, 16);   // combine halves (dup on c, c+16)
    acc += bs[c];

    float m = acc;
    #pragma unroll
    for (int off = 8; off; off >>= 1)
        m = fmaxf(m, __shfl_xor_sync(0xffffffffu, m, off));
    float ex = __expf(acc - m);
    float ss = ex;
    #pragma unroll
    for (int off = 8; off; off >>= 1)
        ss += __shfl_xor_sync(0xffffffffu, ss, off);
    float res = acc - m - __logf(ss);
    if (lane < CDIM) out[(size_t)edge * CDIM + lane] = res;
}

// ---------------------------------------------------------------- launch
extern "C" void kernel_launch(void* const* d_in, const int* in_sizes, int n_in,
                              void* d_out, int out_size) {
    const float* x     = (const float*)d_in[0];
    const int*   ei    = (const int*)  d_in[1];
    const float* eattr = (const float*)d_in[2];
    const float* W1 = (const float*)d_in[3];  const float* b1 = (const float*)d_in[4];
    const float* W2 = (const float*)d_in[5];  const float* b2 = (const float*)d_in[6];
    const float* W3 = (const float*)d_in[7];  const float* b3 = (const float*)d_in[8];
    const float* Wfc = (const float*)d_in[9]; const float* bfc = (const float*)d_in[10];
    float* out = (float*)d_out;

    int n = in_sizes[0] / HDIM;
    int e = in_sizes[1] / 2;
    const int* src = ei;
    const int* dst = ei + e;

    cudaFuncSetAttribute(k_gemm128, cudaFuncAttributeMaxDynamicSharedMemorySize, GEMM_SMEM);

    int bn   = (n + 255) / 256;
    int be   = (e + 255) / 256;
    int bn32 = (n * 32 + 255) / 256;
    int bsc  = (int)(((long long)e * 32 + 255) / 256);
    int bgem = (n + GEMM_BM - 1) / GEMM_BM;
    int bedg = (e + 7) / 8;

    // degree normalization
    k_deg_init <<<bn, 256>>>(n);
    k_deg_count<<<be, 256>>>(dst, e);
    k_deg_rsqrt<<<bn, 256>>>(n);

    // layer 1 (input = x)
    k_gemm128 <<<bgem, 256, GEMM_SMEM>>>(x, W1, n);
    k_zero    <<<bn32, 256>>>(n * 32);
    k_scatter <<<bsc, 256>>>(src, dst, e);
    k_finalize<<<bn32, 256>>>(b1, n);

    // layer 2 (input = g_h)
    k_gemm128 <<<bgem, 256, GEMM_SMEM>>>(nullptr, W2, n);
    k_zero    <<<bn32, 256>>>(n * 32);
    k_scatter <<<bsc, 256>>>(src, dst, e);
    k_finalize<<<bn32, 256>>>(b2, n);

    // layer 3
    k_gemm128 <<<bgem, 256, GEMM_SMEM>>>(nullptr, W3, n);
    k_zero    <<<bn32, 256>>>(n * 32);
    k_scatter <<<bsc, 256>>>(src, dst, e);
    k_finalize<<<bn32, 256>>>(b3, n);

    // edge classifier + log_softmax
    k_edge<<<bedg, 256>>>(src, dst, eattr, Wfc, bfc, out, e);
}

// round 2
// speedup vs baseline: 1.2239x; 1.2239x over previous
#include <cuda_runtime.h>
#include <math.h>

#define HDIM   128
#define NMAX   100000
#define EMAX   1000000
#define CDIM   16
#define FDIM   288   // 2*HDIM + 32

// Scratch (static device globals — allocation-free per harness rules)
__device__ float g_dinv[NMAX];
__device__ float g_lin[(size_t)NMAX * HDIM];
__device__ float g_agg[(size_t)NMAX * HDIM];

// ---------------------------------------------------------------- degree
__global__ void k_deg_init(int n) {
    int i = blockIdx.x * blockDim.x + threadIdx.x;
    if (i < n) g_dinv[i] = 1.0f;           // deg starts at 1 (self-loop)
}
__global__ void k_deg_count(const int* __restrict__ dst, int e) {
    int i = blockIdx.x * blockDim.x + threadIdx.x;
    if (i < e) atomicAdd(&g_dinv[dst[i]], 1.0f);
}
__global__ void k_deg_rsqrt(int n) {
    int i = blockIdx.x * blockDim.x + threadIdx.x;
    if (i < n) g_dinv[i] = rsqrtf(g_dinv[i]);
}

// ---------------------------------------------------------------- GEMM: lin = act(A) @ W   (A: M x 128, W: 128 x 128)
// A == nullptr means "read g_agg" (previous layer output, pre-ReLU).
// relu flag applies ReLU to A elements at load time (fused activation).
#define GEMM_BM 64
#define GEMM_SMEM ((128*128 + GEMM_BM*128) * 4)
__global__ void k_gemm128(const float* __restrict__ Aext,
                          const float* __restrict__ W, int M, int relu) {
    extern __shared__ float sm[];
    float*  Ws  = sm;                 // 128*128
    float*  As  = sm + 128 * 128;     // BM*128
    float4* Ws4 = (float4*)Ws;
    float4* As4 = (float4*)As;

    const float* A = Aext ? Aext : g_agg;
    int tid = threadIdx.x;

    // load W (4096 float4, 16 per thread)
    const float4* W4 = (const float4*)W;
    #pragma unroll
    for (int i = 0; i < 16; i++) Ws4[tid + i * 256] = W4[tid + i * 256];

    // load A tile (BM*32 = 2048 float4, 8 per thread), fused ReLU, zero-pad OOB
    int row0 = blockIdx.x * GEMM_BM;
    const float4* A4 = (const float4*)A;
    #pragma unroll
    for (int i = 0; i < 8; i++) {
        int idx = tid + i * 256;       // 0..2047
        int r   = idx >> 5;
        float4 v = make_float4(0.f, 0.f, 0.f, 0.f);
        if (row0 + r < M) {
            v = A4[(size_t)(row0 + r) * 32 + (idx & 31)];
            if (relu) {
                v.x = fmaxf(v.x, 0.f); v.y = fmaxf(v.y, 0.f);
                v.z = fmaxf(v.z, 0.f); v.w = fmaxf(v.w, 0.f);
            }
        }
        As4[idx] = v;
    }
    __syncthreads();

    int warp = tid >> 5, lane = tid & 31;
    int rbase = warp * 8;

    float4 acc[8];
    #pragma unroll
    for (int r = 0; r < 8; r++) acc[r] = make_float4(0.f, 0.f, 0.f, 0.f);

    #pragma unroll 8
    for (int k = 0; k < 128; k++) {
        float4 w = Ws4[k * 32 + lane];
        #pragma unroll
        for (int r = 0; r < 8; r++) {
            float a = As[(rbase + r) * 128 + k];
            acc[r].x += a * w.x; acc[r].y += a * w.y;
            acc[r].z += a * w.z; acc[r].w += a * w.w;
        }
    }

    float4* O4 = (float4*)g_lin;
    #pragma unroll
    for (int r = 0; r < 8; r++) {
        int row = row0 + rbase + r;
        if (row < M) O4[(size_t)row * 32 + lane] = acc[r];
    }
}

// ---------------------------------------------------------------- init agg = lin*dinv^2 + b  (self-loop + bias fused)
__global__ void k_initagg(const float* __restrict__ b, int n) {
    int idx = blockIdx.x * blockDim.x + threadIdx.x;  // over n*32 float4
    if (idx >= n * 32) return;
    int row = idx >> 5, c4 = idx & 31;
    float di = g_dinv[row];
    float sl = di * di;
    float4 l  = ((const float4*)g_lin)[idx];
    float4 bb = ((const float4*)b)[c4];
    float4 o;
    o.x = fmaf(l.x, sl, bb.x);
    o.y = fmaf(l.y, sl, bb.y);
    o.z = fmaf(l.z, sl, bb.z);
    o.w = fmaf(l.w, sl, bb.w);
    ((float4*)g_agg)[idx] = o;
}

// ---------------------------------------------------------------- scatter: agg[dst] += lin[src] * dinv[src]*dinv[dst]
// One warp per edge; each lane owns one float4 (4 cols). Vector red (16B/op).
__global__ void k_scatter(const int* __restrict__ src, const int* __restrict__ dst, int e) {
    int g    = blockIdx.x * blockDim.x + threadIdx.x;
    int edge = g >> 5;
    int lane = g & 31;
    if (edge >= e) return;
    int s = src[edge], d = dst[edge];
    float norm = g_dinv[s] * g_dinv[d];
    float4 v = ((const float4*)(g_lin + (size_t)s * HDIM))[lane];
    float4* ad = ((float4*)(g_agg + (size_t)d * HDIM)) + lane;
    asm volatile("red.global.add.v4.f32 [%0], {%1, %2, %3, %4};"
                 :: "l"(ad), "f"(v.x * norm), "f"(v.y * norm),
                    "f"(v.z * norm), "f"(v.w * norm)
                 : "memory");
}

// ---------------------------------------------------------------- edge classifier + log_softmax
// One warp per edge. h = relu(g_agg) applied at gather time.
__global__ void k_edge(const int* __restrict__ src, const int* __restrict__ dst,
                       const float* __restrict__ eattr,
                       const float* __restrict__ Wfc, const float* __restrict__ bfc,
                       float* __restrict__ out, int e) {
    __shared__ float Ws[FDIM * CDIM];   // 18 KB
    __shared__ float bs[CDIM];
    __shared__ float feat[8][FDIM];

    int tid = threadIdx.x;
    for (int i = tid; i < FDIM * CDIM; i += 256) Ws[i] = Wfc[i];
    if (tid < CDIM) bs[tid] = bfc[tid];
    __syncthreads();

    int warp = tid >> 5, lane = tid & 31;
    int edge = blockIdx.x * 8 + warp;
    if (edge >= e) return;

    int s = src[edge], d = dst[edge];
    float4* f4 = (float4*)feat[warp];
    float4 hs = ((const float4*)(g_agg + (size_t)s * HDIM))[lane];
    float4 hd = ((const float4*)(g_agg + (size_t)d * HDIM))[lane];
    hs.x = fmaxf(hs.x, 0.f); hs.y = fmaxf(hs.y, 0.f);
    hs.z = fmaxf(hs.z, 0.f); hs.w = fmaxf(hs.w, 0.f);
    hd.x = fmaxf(hd.x, 0.f); hd.y = fmaxf(hd.y, 0.f);
    hd.z = fmaxf(hd.z, 0.f); hd.w = fmaxf(hd.w, 0.f);
    f4[lane]      = hs;
    f4[32 + lane] = hd;
    if (lane < 8)
        f4[64 + lane] = ((const float4*)(eattr + (size_t)edge * 32))[lane];
    __syncwarp();

    int c    = lane & 15;
    int half = lane >> 4;           // split K: 144 each
    const float* fw = feat[warp];
    float acc = 0.f;
    int k0 = half * 144;
    #pragma unroll 8
    for (int k = k0; k < k0 + 144; k++)
        acc = fmaf(fw[k], Ws[k * CDIM + c], acc);
    acc += __shfl_xor_sync(0xffffffffu, acc, 16);   // combine halves
    acc += bs[c];

    float m = acc;
    #pragma unroll
    for (int off = 8; off; off >>= 1)
        m = fmaxf(m, __shfl_xor_sync(0xffffffffu, m, off));
    float ex = __expf(acc - m);
    float ss = ex;
    #pragma unroll
    for (int off = 8; off; off >>= 1)
        ss += __shfl_xor_sync(0xffffffffu, ss, off);
    float res = acc - m - __logf(ss);
    if (lane < CDIM) out[(size_t)edge * CDIM + lane] = res;
}

// ---------------------------------------------------------------- launch
extern "C" void kernel_launch(void* const* d_in, const int* in_sizes, int n_in,
                              void* d_out, int out_size) {
    const float* x     = (const float*)d_in[0];
    const int*   ei    = (const int*)  d_in[1];
    const float* eattr = (const float*)d_in[2];
    const float* W1 = (const float*)d_in[3];  const float* b1 = (const float*)d_in[4];
    const float* W2 = (const float*)d_in[5];  const float* b2 = (const float*)d_in[6];
    const float* W3 = (const float*)d_in[7];  const float* b3 = (const float*)d_in[8];
    const float* Wfc = (const float*)d_in[9]; const float* bfc = (const float*)d_in[10];
    float* out = (float*)d_out;

    int n = in_sizes[0] / HDIM;
    int e = in_sizes[1] / 2;
    const int* src = ei;
    const int* dst = ei + e;

    cudaFuncSetAttribute(k_gemm128, cudaFuncAttributeMaxDynamicSharedMemorySize, GEMM_SMEM);

    int bn   = (n + 255) / 256;
    int be   = (e + 255) / 256;
    int bn32 = (n * 32 + 255) / 256;
    int bsc  = (int)(((long long)e * 32 + 255) / 256);
    int bgem = (n + GEMM_BM - 1) / GEMM_BM;
    int bedg = (e + 7) / 8;

    // degree normalization
    k_deg_init <<<bn, 256>>>(n);
    k_deg_count<<<be, 256>>>(dst, e);
    k_deg_rsqrt<<<bn, 256>>>(n);

    // layer 1 (input = x, no activation)
    k_gemm128 <<<bgem, 256, GEMM_SMEM>>>(x, W1, n, 0);
    k_initagg <<<bn32, 256>>>(b1, n);
    k_scatter <<<bsc, 256>>>(src, dst, e);

    // layer 2 (input = relu(g_agg))
    k_gemm128 <<<bgem, 256, GEMM_SMEM>>>(nullptr, W2, n, 1);
    k_initagg <<<bn32, 256>>>(b2, n);
    k_scatter <<<bsc, 256>>>(src, dst, e);

    // layer 3
    k_gemm128 <<<bgem, 256, GEMM_SMEM>>>(nullptr, W3, n, 1);
    k_initagg <<<bn32, 256>>>(b3, n);
    k_scatter <<<bsc, 256>>>(src, dst, e);

    // edge classifier + log_softmax (relu fused into gather)
    k_edge<<<bedg, 256>>>(src, dst, eattr, Wfc, bfc, out, e);
}

// round 3
// speedup vs baseline: 1.4009x; 1.1447x over previous
#include <cuda_runtime.h>
#include <math.h>

#define HDIM   128
#define NMAX   100000
#define EMAX   1000000
#define CDIM   16
#define FDIM   288   // 2*HDIM + 32
#define SCAN_B 1024

// Scratch (static device globals — allocation-free per harness rules)
__device__ float g_dinv[NMAX];
__device__ float g_lin[(size_t)NMAX * HDIM];
__device__ float g_agg[(size_t)NMAX * HDIM];
__device__ int   g_cnt[NMAX];
__device__ int   g_rowptr[NMAX + 1];
__device__ int   g_cursor[NMAX];
__device__ int   g_csrsrc[EMAX];
__device__ int   g_blocksum[128];
__device__ int   g_blockoff[128];

// ---------------------------------------------------------------- CSR build
__global__ void k_cnt_zero(int n) {
    int i = blockIdx.x * blockDim.x + threadIdx.x;
    if (i < n) g_cnt[i] = 0;
}
__global__ void k_hist(const int* __restrict__ dst, int e) {
    int i = blockIdx.x * blockDim.x + threadIdx.x;
    if (i < e) atomicAdd(&g_cnt[dst[i]], 1);
}
__global__ void k_dinv(int n) {
    int i = blockIdx.x * blockDim.x + threadIdx.x;
    if (i < n) g_dinv[i] = rsqrtf((float)g_cnt[i] + 1.0f);  // +1 self-loop
}
// block-level exclusive scan of g_cnt -> g_rowptr (partial), block sums out
__global__ void k_scan1(int n) {
    __shared__ int sm[SCAN_B];
    int i = blockIdx.x * SCAN_B + threadIdx.x;
    int v = (i < n) ? g_cnt[i] : 0;
    sm[threadIdx.x] = v;
    __syncthreads();
    #pragma unroll
    for (int off = 1; off < SCAN_B; off <<= 1) {
        int t = (threadIdx.x >= off) ? sm[threadIdx.x - off] : 0;
        __syncthreads();
        sm[threadIdx.x] += t;
        __syncthreads();
    }
    if (i < n) g_rowptr[i] = sm[threadIdx.x] - v;   // exclusive
    if (threadIdx.x == SCAN_B - 1) g_blocksum[blockIdx.x] = sm[SCAN_B - 1];
}
// scan the block sums (nb <= 128)
__global__ void k_scan2(int nb) {
    __shared__ int sm[128];
    int t = threadIdx.x;
    int v = (t < nb) ? g_blocksum[t] : 0;
    sm[t] = v;
    __syncthreads();
    #pragma unroll
    for (int off = 1; off < 128; off <<= 1) {
        int x = (t >= off) ? sm[t - off] : 0;
        __syncthreads();
        sm[t] += x;
        __syncthreads();
    }
    if (t < nb) g_blockoff[t] = sm[t] - v;          // exclusive
}
// add block offsets, init cursor, set rowptr[n]=e
__global__ void k_scan3(int n, int e) {
    int i = blockIdx.x * SCAN_B + threadIdx.x;
    if (i < n) {
        int r = g_rowptr[i] + g_blockoff[blockIdx.x];
        g_rowptr[i] = r;
        g_cursor[i] = r;
    }
    if (i == 0) g_rowptr[n] = e;
}
__global__ void k_fill(const int* __restrict__ src, const int* __restrict__ dst, int e) {
    int i = blockIdx.x * blockDim.x + threadIdx.x;
    if (i < e) {
        int pos = atomicAdd(&g_cursor[dst[i]], 1);
        g_csrsrc[pos] = src[i];
    }
}

// ---------------------------------------------------------------- GEMM: lin = act(A) @ W   (A: M x 128, W: 128 x 128)
// A == nullptr means "read g_agg" (previous layer output, pre-ReLU).
#define GEMM_BM 64
#define GEMM_SMEM ((128*128 + GEMM_BM*128) * 4)
__global__ void k_gemm128(const float* __restrict__ Aext,
                          const float* __restrict__ W, int M, int relu) {
    extern __shared__ float sm[];
    float*  Ws  = sm;                 // 128*128
    float*  As  = sm + 128 * 128;     // BM*128
    float4* Ws4 = (float4*)Ws;
    float4* As4 = (float4*)As;

    const float* A = Aext ? Aext : g_agg;
    int tid = threadIdx.x;

    const float4* W4 = (const float4*)W;
    #pragma unroll
    for (int i = 0; i < 16; i++) Ws4[tid + i * 256] = W4[tid + i * 256];

    int row0 = blockIdx.x * GEMM_BM;
    const float4* A4 = (const float4*)A;
    #pragma unroll
    for (int i = 0; i < 8; i++) {
        int idx = tid + i * 256;       // 0..2047
        int r   = idx >> 5;
        float4 v = make_float4(0.f, 0.f, 0.f, 0.f);
        if (row0 + r < M) {
            v = A4[(size_t)(row0 + r) * 32 + (idx & 31)];
            if (relu) {
                v.x = fmaxf(v.x, 0.f); v.y = fmaxf(v.y, 0.f);
                v.z = fmaxf(v.z, 0.f); v.w = fmaxf(v.w, 0.f);
            }
        }
        As4[idx] = v;
    }
    __syncthreads();

    int warp = tid >> 5, lane = tid & 31;
    int rbase = warp * 8;

    float4 acc[8];
    #pragma unroll
    for (int r = 0; r < 8; r++) acc[r] = make_float4(0.f, 0.f, 0.f, 0.f);

    #pragma unroll 8
    for (int k = 0; k < 128; k++) {
        float4 w = Ws4[k * 32 + lane];
        #pragma unroll
        for (int r = 0; r < 8; r++) {
            float a = As[(rbase + r) * 128 + k];
            acc[r].x += a * w.x; acc[r].y += a * w.y;
            acc[r].z += a * w.z; acc[r].w += a * w.w;
        }
    }

    float4* O4 = (float4*)g_lin;
    #pragma unroll
    for (int r = 0; r < 8; r++) {
        int row = row0 + rbase + r;
        if (row < M) O4[(size_t)row * 32 + lane] = acc[r];
    }
}

// ---------------------------------------------------------------- aggregate (CSR gather, no atomics)
// One warp per dst node: agg[d] = b + lin[d]*dinv[d]^2 + sum_{s in N(d)} lin[s]*dinv[s]*dinv[d]
__global__ void k_aggregate(const float* __restrict__ b, int n) {
    int gwarp = (blockIdx.x * blockDim.x + threadIdx.x) >> 5;
    int lane  = threadIdx.x & 31;
    if (gwarp >= n) return;

    float di = g_dinv[gwarp];
    const float4* lin4 = (const float4*)g_lin;

    float4 bb = ((const float4*)b)[lane];
    float4 l  = lin4[(size_t)gwarp * 32 + lane];
    float sl  = di * di;
    float4 acc;
    acc.x = fmaf(l.x, sl, bb.x);
    acc.y = fmaf(l.y, sl, bb.y);
    acc.z = fmaf(l.z, sl, bb.z);
    acc.w = fmaf(l.w, sl, bb.w);

    int beg = g_rowptr[gwarp];
    int end = g_rowptr[gwarp + 1];
    for (int j = beg; j < end; j++) {
        int s = g_csrsrc[j];
        float norm = g_dinv[s] * di;
        float4 v = lin4[(size_t)s * 32 + lane];
        acc.x = fmaf(v.x, norm, acc.x);
        acc.y = fmaf(v.y, norm, acc.y);
        acc.z = fmaf(v.z, norm, acc.z);
        acc.w = fmaf(v.w, norm, acc.w);
    }
    ((float4*)g_agg)[(size_t)gwarp * 32 + lane] = acc;
}

// ---------------------------------------------------------------- edge classifier + log_softmax
// One warp per edge. h = relu(g_agg) applied at gather time.
__global__ void k_edge(const int* __restrict__ src, const int* __restrict__ dst,
                       const float* __restrict__ eattr,
                       const float* __restrict__ Wfc, const float* __restrict__ bfc,
                       float* __restrict__ out, int e) {
    __shared__ float Ws[FDIM * CDIM];   // 18 KB
    __shared__ float bs[CDIM];
    __shared__ float feat[8][FDIM];

    int tid = threadIdx.x;
    for (int i = tid; i < FDIM * CDIM; i += 256) Ws[i] = Wfc[i];
    if (tid < CDIM) bs[tid] = bfc[tid];
    __syncthreads();

    int warp = tid >> 5, lane = tid & 31;
    int edge = blockIdx.x * 8 + warp;
    if (edge >= e) return;

    int s = src[edge], d = dst[edge];
    float4* f4 = (float4*)feat[warp];
    float4 hs = ((const float4*)(g_agg + (size_t)s * HDIM))[lane];
    float4 hd = ((const float4*)(g_agg + (size_t)d * HDIM))[lane];
    hs.x = fmaxf(hs.x, 0.f); hs.y = fmaxf(hs.y, 0.f);
    hs.z = fmaxf(hs.z, 0.f); hs.w = fmaxf(hs.w, 0.f);
    hd.x = fmaxf(hd.x, 0.f); hd.y = fmaxf(hd.y, 0.f);
    hd.z = fmaxf(hd.z, 0.f); hd.w = fmaxf(hd.w, 0.f);
    f4[lane]      = hs;
    f4[32 + lane] = hd;
    if (lane < 8)
        f4[64 + lane] = ((const float4*)(eattr + (size_t)edge * 32))[lane];
    __syncwarp();

    int c    = lane & 15;
    int half = lane >> 4;           // split K: 144 each
    const float* fw = feat[warp];
    float acc = 0.f;
    int k0 = half * 144;
    #pragma unroll 8
    for (int k = k0; k < k0 + 144; k++)
        acc = fmaf(fw[k], Ws[k * CDIM + c], acc);
    acc += __shfl_xor_sync(0xffffffffu, acc, 16);   // combine halves
    acc += bs[c];

    float m = acc;
    #pragma unroll
    for (int off = 8; off; off >>= 1)
        m = fmaxf(m, __shfl_xor_sync(0xffffffffu, m, off));
    float ex = __expf(acc - m);
    float ss = ex;
    #pragma unroll
    for (int off = 8; off; off >>= 1)
        ss += __shfl_xor_sync(0xffffffffu, ss, off);
    float res = acc - m - __logf(ss);
    if (lane < CDIM) out[(size_t)edge * CDIM + lane] = res;
}

// ---------------------------------------------------------------- launch
extern "C" void kernel_launch(void* const* d_in, const int* in_sizes, int n_in,
                              void* d_out, int out_size) {
    const float* x     = (const float*)d_in[0];
    const int*   ei    = (const int*)  d_in[1];
    const float* eattr = (const float*)d_in[2];
    const float* W1 = (const float*)d_in[3];  const float* b1 = (const float*)d_in[4];
    const float* W2 = (const float*)d_in[5];  const float* b2 = (const float*)d_in[6];
    const float* W3 = (const float*)d_in[7];  const float* b3 = (const float*)d_in[8];
    const float* Wfc = (const float*)d_in[9]; const float* bfc = (const float*)d_in[10];
    float* out = (float*)d_out;

    int n = in_sizes[0] / HDIM;
    int e = in_sizes[1] / 2;
    const int* src = ei;
    const int* dst = ei + e;

    cudaFuncSetAttribute(k_gemm128, cudaFuncAttributeMaxDynamicSharedMemorySize, GEMM_SMEM);

    int bn   = (n + 255) / 256;
    int be   = (e + 255) / 256;
    int bgem = (n + GEMM_BM - 1) / GEMM_BM;
    int bagg = (n + 7) / 8;           // 8 warps per 256-thread block
    int bedg = (e + 7) / 8;
    int nscan = (n + SCAN_B - 1) / SCAN_B;

    // ---- CSR build (once; reused by all 3 layers) + degree norm
    k_cnt_zero<<<bn, 256>>>(n);
    k_hist    <<<be, 256>>>(dst, e);
    k_dinv    <<<bn, 256>>>(n);
    k_scan1   <<<nscan, SCAN_B>>>(n);
    k_scan2   <<<1, 128>>>(nscan);
    k_scan3   <<<nscan, SCAN_B>>>(n, e);
    k_fill    <<<be, 256>>>(src, dst, e);

    // ---- layer 1 (input = x, no activation)
    k_gemm128  <<<bgem, 256, GEMM_SMEM>>>(x, W1, n, 0);
    k_aggregate<<<bagg, 256>>>(b1, n);

    // ---- layer 2 (input = relu(g_agg))
    k_gemm128  <<<bgem, 256, GEMM_SMEM>>>(nullptr, W2, n, 1);
    k_aggregate<<<bagg, 256>>>(b2, n);

    // ---- layer 3
    k_gemm128  <<<bgem, 256, GEMM_SMEM>>>(nullptr, W3, n, 1);
    k_aggregate<<<bagg, 256>>>(b3, n);

    // ---- edge classifier + log_softmax (relu fused into gather)
    k_edge<<<bedg, 256>>>(src, dst, eattr, Wfc, bfc, out, e);
}

// round 4
// speedup vs baseline: 3.5486x; 2.5331x over previous
#include <cuda_runtime.h>
#include <math.h>

#define HDIM   128
#define NMAX   100000
#define EMAX   1000000
#define CDIM   16
#define SCAN_B 1024

// Scratch (static device globals — allocation-free per harness rules)
__device__ float g_dinv[NMAX];
__device__ float g_lin[(size_t)NMAX * HDIM];
__device__ float g_agg[(size_t)NMAX * HDIM];
__device__ float g_P  [(size_t)NMAX * 32];     // per-node [P_src(16) | P_dst(16)]
__device__ int   g_cnt[NMAX];
__device__ int   g_rowptr[NMAX + 1];
__device__ int   g_cursor[NMAX];
__device__ int   g_csrsrc[EMAX];
__device__ int   g_blocksum[128];
__device__ int   g_blockoff[128];

// ---------------------------------------------------------------- CSR build
__global__ void k_cnt_zero(int n) {
    int i = blockIdx.x * blockDim.x + threadIdx.x;
    if (i < n) g_cnt[i] = 0;
}
__global__ void k_hist(const int* __restrict__ dst, int e) {
    int i = blockIdx.x * blockDim.x + threadIdx.x;
    if (i < e) atomicAdd(&g_cnt[dst[i]], 1);
}
__global__ void k_dinv(int n) {
    int i = blockIdx.x * blockDim.x + threadIdx.x;
    if (i < n) g_dinv[i] = rsqrtf((float)g_cnt[i] + 1.0f);  // +1 self-loop
}
__global__ void k_scan1(int n) {
    __shared__ int sm[SCAN_B];
    int i = blockIdx.x * SCAN_B + threadIdx.x;
    int v = (i < n) ? g_cnt[i] : 0;
    sm[threadIdx.x] = v;
    __syncthreads();
    #pragma unroll
    for (int off = 1; off < SCAN_B; off <<= 1) {
        int t = (threadIdx.x >= off) ? sm[threadIdx.x - off] : 0;
        __syncthreads();
        sm[threadIdx.x] += t;
        __syncthreads();
    }
    if (i < n) g_rowptr[i] = sm[threadIdx.x] - v;   // exclusive
    if (threadIdx.x == SCAN_B - 1) g_blocksum[blockIdx.x] = sm[SCAN_B - 1];
}
__global__ void k_scan2(int nb) {
    __shared__ int sm[128];
    int t = threadIdx.x;
    int v = (t < nb) ? g_blocksum[t] : 0;
    sm[t] = v;
    __syncthreads();
    #pragma unroll
    for (int off = 1; off < 128; off <<= 1) {
        int x = (t >= off) ? sm[t - off] : 0;
        __syncthreads();
        sm[t] += x;
        __syncthreads();
    }
    if (t < nb) g_blockoff[t] = sm[t] - v;          // exclusive
}
__global__ void k_scan3(int n, int e) {
    int i = blockIdx.x * SCAN_B + threadIdx.x;
    if (i < n) {
        int r = g_rowptr[i] + g_blockoff[blockIdx.x];
        g_rowptr[i] = r;
        g_cursor[i] = r;
    }
    if (i == 0) g_rowptr[n] = e;
}
__global__ void k_fill(const int* __restrict__ src, const int* __restrict__ dst, int e) {
    int i = blockIdx.x * blockDim.x + threadIdx.x;
    if (i < e) {
        int pos = atomicAdd(&g_cursor[dst[i]], 1);
        g_csrsrc[pos] = src[i];
    }
}

// ---------------------------------------------------------------- GEMM: lin = act(A) @ W   (A: M x 128, W: 128 x 128)
#define GEMM_BM 64
#define GEMM_SMEM ((128*128 + GEMM_BM*128) * 4)
__global__ void k_gemm128(const float* __restrict__ Aext,
                          const float* __restrict__ W, int M, int relu) {
    extern __shared__ float sm[];
    float*  Ws  = sm;                 // 128*128
    float*  As  = sm + 128 * 128;     // BM*128
    float4* Ws4 = (float4*)Ws;
    float4* As4 = (float4*)As;

    const float* A = Aext ? Aext : g_agg;
    int tid = threadIdx.x;

    const float4* W4 = (const float4*)W;
    #pragma unroll
    for (int i = 0; i < 16; i++) Ws4[tid + i * 256] = W4[tid + i * 256];

    int row0 = blockIdx.x * GEMM_BM;
    const float4* A4 = (const float4*)A;
    #pragma unroll
    for (int i = 0; i < 8; i++) {
        int idx = tid + i * 256;       // 0..2047
        int r   = idx >> 5;
        float4 v = make_float4(0.f, 0.f, 0.f, 0.f);
        if (row0 + r < M) {
            v = A4[(size_t)(row0 + r) * 32 + (idx & 31)];
            if (relu) {
                v.x = fmaxf(v.x, 0.f); v.y = fmaxf(v.y, 0.f);
                v.z = fmaxf(v.z, 0.f); v.w = fmaxf(v.w, 0.f);
            }
        }
        As4[idx] = v;
    }
    __syncthreads();

    int warp = tid >> 5, lane = tid & 31;
    int rbase = warp * 8;

    float4 acc[8];
    #pragma unroll
    for (int r = 0; r < 8; r++) acc[r] = make_float4(0.f, 0.f, 0.f, 0.f);

    #pragma unroll 8
    for (int k = 0; k < 128; k++) {
        float4 w = Ws4[k * 32 + lane];
        #pragma unroll
        for (int r = 0; r < 8; r++) {
            float a = As[(rbase + r) * 128 + k];
            acc[r].x += a * w.x; acc[r].y += a * w.y;
            acc[r].z += a * w.z; acc[r].w += a * w.w;
        }
    }

    float4* O4 = (float4*)g_lin;
    #pragma unroll
    for (int r = 0; r < 8; r++) {
        int row = row0 + rbase + r;
        if (row < M) O4[(size_t)row * 32 + lane] = acc[r];
    }
}

// ---------------------------------------------------------------- aggregate (CSR gather, no atomics, MLP via warp batching)
__global__ void k_aggregate(const float* __restrict__ b, int n) {
    int gwarp = (blockIdx.x * blockDim.x + threadIdx.x) >> 5;
    int lane  = threadIdx.x & 31;
    if (gwarp >= n) return;

    float di = g_dinv[gwarp];
    const float4* lin4 = (const float4*)g_lin;

    float4 bb = ((const float4*)b)[lane];
    float4 l  = lin4[(size_t)gwarp * 32 + lane];
    float sl  = di * di;
    float4 acc;
    acc.x = fmaf(l.x, sl, bb.x);
    acc.y = fmaf(l.y, sl, bb.y);
    acc.z = fmaf(l.z, sl, bb.z);
    acc.w = fmaf(l.w, sl, bb.w);

    int beg = g_rowptr[gwarp];
    int end = g_rowptr[gwarp + 1];
    for (int base = beg; base < end; base += 32) {
        int cnt = end - base; if (cnt > 32) cnt = 32;
        // coalesced batch load of up to 32 source ids + norms
        int   sj = (base + lane < end) ? g_csrsrc[base + lane] : 0;
        float nj = (base + lane < end) ? g_dinv[sj] * di : 0.f;
        #pragma unroll 8
        for (int t = 0; t < cnt; t++) {
            int   s  = __shfl_sync(0xffffffffu, sj, t);
            float nn = __shfl_sync(0xffffffffu, nj, t);
            float4 v = lin4[(size_t)s * 32 + lane];
            acc.x = fmaf(v.x, nn, acc.x);
            acc.y = fmaf(v.y, nn, acc.y);
            acc.z = fmaf(v.z, nn, acc.z);
            acc.w = fmaf(v.w, nn, acc.w);
        }
    }
    ((float4*)g_agg)[(size_t)gwarp * 32 + lane] = acc;
}

// ---------------------------------------------------------------- node projection: P[n] = [relu(h)@W_src | relu(h)@W_dst]
// Warp per node; h row lives in registers, broadcast via shuffle.
__global__ void k_proj(const float* __restrict__ Wfc, int n) {
    __shared__ float Ws[128 * 32];   // Wp[k][l]: l<16 -> Wfc[k][l], l>=16 -> Wfc[128+k][l-16]
    int tid = threadIdx.x;
    for (int idx = tid; idx < 128 * 32; idx += 256) {
        int k = idx >> 5, l = idx & 31;
        Ws[idx] = (l < 16) ? Wfc[k * 16 + l] : Wfc[(128 + k) * 16 + (l - 16)];
    }
    __syncthreads();

    int warp = tid >> 5, lane = tid & 31;
    int node = blockIdx.x * 8 + warp;
    if (node >= n) return;

    float4 h = ((const float4*)g_agg)[(size_t)node * 32 + lane];
    h.x = fmaxf(h.x, 0.f); h.y = fmaxf(h.y, 0.f);
    h.z = fmaxf(h.z, 0.f); h.w = fmaxf(h.w, 0.f);

    float acc = 0.f;
    #pragma unroll
    for (int k = 0; k < 128; k++) {
        float comp = (k & 3) == 0 ? h.x : (k & 3) == 1 ? h.y : (k & 3) == 2 ? h.z : h.w;
        float a = __shfl_sync(0xffffffffu, comp, k >> 2);
        acc = fmaf(a, Ws[k * 32 + lane], acc);
    }
    g_P[(size_t)node * 32 + lane] = acc;
}

// ---------------------------------------------------------------- edge output: out = logsoftmax(P_src[s] + P_dst[d] + ea@We + b)
#define EB 16   // edges per block (256 threads = 16 edges x 16 classes)
__global__ void k_edge2(const int* __restrict__ src, const int* __restrict__ dst,
                        const float* __restrict__ eattr,
                        const float* __restrict__ Wfc, const float* __restrict__ bfc,
                        float* __restrict__ out, int e) {
    __shared__ float We[32 * 16];    // Wfc rows 256..287
    __shared__ float bs[CDIM];
    __shared__ float ea[EB][33];     // padded to kill bank conflicts

    int tid = threadIdx.x;
    for (int i = tid; i < 32 * 16; i += 256) We[i] = Wfc[256 * 16 + i];
    if (tid < CDIM) bs[tid] = bfc[tid];

    int e0 = blockIdx.x * EB;
    // stage eattr tile: 16 edges x 32 floats, coalesced float4 loads
    if (tid < 128) {
        int el = tid >> 3, q = tid & 7;
        if (e0 + el < e) {
            float4 v = ((const float4*)(eattr + (size_t)(e0 + el) * 32))[q];
            ea[el][q * 4 + 0] = v.x; ea[el][q * 4 + 1] = v.y;
            ea[el][q * 4 + 2] = v.z; ea[el][q * 4 + 3] = v.w;
        }
    }
    __syncthreads();

    int el = tid >> 4, c = tid & 15;
    int edge = e0 + el;
    bool valid = edge < e;
    int ce = valid ? edge : e - 1;

    int s = src[ce], d = dst[ce];
    float acc = bs[c] + g_P[(size_t)s * 32 + c] + g_P[(size_t)d * 32 + 16 + c];
    #pragma unroll
    for (int k = 0; k < 32; k++)
        acc = fmaf(ea[el][k], We[k * 16 + c], acc);

    // log-softmax across the 16-thread group (xor shuffles stay in-group)
    float m = acc;
    #pragma unroll
    for (int off = 8; off; off >>= 1)
        m = fmaxf(m, __shfl_xor_sync(0xffffffffu, m, off));
    float ex = __expf(acc - m);
    float ss = ex;
    #pragma unroll
    for (int off = 8; off; off >>= 1)
        ss += __shfl_xor_sync(0xffffffffu, ss, off);
    float res = acc - m - __logf(ss);
    if (valid) out[(size_t)edge * CDIM + c] = res;
}

// ---------------------------------------------------------------- launch
extern "C" void kernel_launch(void* const* d_in, const int* in_sizes, int n_in,
                              void* d_out, int out_size) {
    const float* x     = (const float*)d_in[0];
    const int*   ei    = (const int*)  d_in[1];
    const float* eattr = (const float*)d_in[2];
    const float* W1 = (const float*)d_in[3];  const float* b1 = (const float*)d_in[4];
    const float* W2 = (const float*)d_in[5];  const float* b2 = (const float*)d_in[6];
    const float* W3 = (const float*)d_in[7];  const float* b3 = (const float*)d_in[8];
    const float* Wfc = (const float*)d_in[9]; const float* bfc = (const float*)d_in[10];
    float* out = (float*)d_out;

    int n = in_sizes[0] / HDIM;
    int e = in_sizes[1] / 2;
    const int* src = ei;
    const int* dst = ei + e;

    cudaFuncSetAttribute(k_gemm128, cudaFuncAttributeMaxDynamicSharedMemorySize, GEMM_SMEM);

    int bn   = (n + 255) / 256;
    int be   = (e + 255) / 256;
    int bgem = (n + GEMM_BM - 1) / GEMM_BM;
    int bagg = (n + 7) / 8;
    int bedg = (e + EB - 1) / EB;
    int nscan = (n + SCAN_B - 1) / SCAN_B;

    // ---- CSR build (once; reused by all 3 layers) + degree norm
    k_cnt_zero<<<bn, 256>>>(n);
    k_hist    <<<be, 256>>>(dst, e);
    k_dinv    <<<bn, 256>>>(n);
    k_scan1   <<<nscan, SCAN_B>>>(n);
    k_scan2   <<<1, 128>>>(nscan);
    k_scan3   <<<nscan, SCAN_B>>>(n, e);
    k_fill    <<<be, 256>>>(src, dst, e);

    // ---- 3 GCN layers
    k_gemm128  <<<bgem, 256, GEMM_SMEM>>>(x, W1, n, 0);
    k_aggregate<<<bagg, 256>>>(b1, n);

    k_gemm128  <<<bgem, 256, GEMM_SMEM>>>(nullptr, W2, n, 1);
    k_aggregate<<<bagg, 256>>>(b2, n);

    k_gemm128  <<<bgem, 256, GEMM_SMEM>>>(nullptr, W3, n, 1);
    k_aggregate<<<bagg, 256>>>(b3, n);

    // ---- factored edge classifier
    k_proj <<<(n + 7) / 8, 256>>>(Wfc, n);
    k_edge2<<<bedg, 256>>>(src, dst, eattr, Wfc, bfc, out, e);
}

// round 5
// speedup vs baseline: 4.1625x; 1.1730x over previous
#include <cuda_runtime.h>
#include <math.h>

#define HDIM   128
#define NMAX   100000
#define EMAX   1000000
#define CDIM   16
#define SCAN_B 1024

// Scratch (static device globals — allocation-free per harness rules)
__device__ float g_dinv[NMAX];
__device__ float g_lin[(size_t)NMAX * HDIM];   // holds lin' = dinv[row] * (act(A)@W)
__device__ float g_agg[(size_t)NMAX * HDIM];
__device__ float g_P  [(size_t)NMAX * 32];     // per-node [P_src(16) | P_dst(16)]
__device__ int   g_cnt[NMAX];
__device__ int   g_rowptr[NMAX + 1];
__device__ int   g_cursor[NMAX];
__device__ int   g_csrsrc[EMAX];
__device__ int   g_blocksum[128];
__device__ int   g_blockoff[128];

// ---------------------------------------------------------------- CSR build
__global__ void k_cnt_zero(int n) {
    int i = blockIdx.x * blockDim.x + threadIdx.x;
    if (i < n) g_cnt[i] = 0;
}
__global__ void k_hist(const int* __restrict__ dst, int e) {
    int i = blockIdx.x * blockDim.x + threadIdx.x;
    if (i < e) atomicAdd(&g_cnt[dst[i]], 1);
}
// scan1 also computes dinv (fused)
__global__ void k_scan1(int n) {
    __shared__ int sm[SCAN_B];
    int i = blockIdx.x * SCAN_B + threadIdx.x;
    int v = (i < n) ? g_cnt[i] : 0;
    if (i < n) g_dinv[i] = rsqrtf((float)v + 1.0f);   // +1 self-loop
    sm[threadIdx.x] = v;
    __syncthreads();
    #pragma unroll
    for (int off = 1; off < SCAN_B; off <<= 1) {
        int t = (threadIdx.x >= off) ? sm[threadIdx.x - off] : 0;
        __syncthreads();
        sm[threadIdx.x] += t;
        __syncthreads();
    }
    if (i < n) g_rowptr[i] = sm[threadIdx.x] - v;     // exclusive
    if (threadIdx.x == SCAN_B - 1) g_blocksum[blockIdx.x] = sm[SCAN_B - 1];
}
__global__ void k_scan2(int nb) {
    __shared__ int sm[128];
    int t = threadIdx.x;
    int v = (t < nb) ? g_blocksum[t] : 0;
    sm[t] = v;
    __syncthreads();
    #pragma unroll
    for (int off = 1; off < 128; off <<= 1) {
        int x = (t >= off) ? sm[t - off] : 0;
        __syncthreads();
        sm[t] += x;
        __syncthreads();
    }
    if (t < nb) g_blockoff[t] = sm[t] - v;            // exclusive
}
__global__ void k_scan3(int n, int e) {
    int i = blockIdx.x * SCAN_B + threadIdx.x;
    if (i < n) {
        int r = g_rowptr[i] + g_blockoff[blockIdx.x];
        g_rowptr[i] = r;
        g_cursor[i] = r;
    }
    if (i == 0) g_rowptr[n] = e;
}
__global__ void k_fill(const int* __restrict__ src, const int* __restrict__ dst, int e) {
    int i = blockIdx.x * blockDim.x + threadIdx.x;
    if (i < e) {
        int pos = atomicAdd(&g_cursor[dst[i]], 1);
        g_csrsrc[pos] = src[i];
    }
}

// ---------------------------------------------------------------- GEMM: lin' = dinv[row] * (act(A) @ W)
#define GEMM_BM 64
#define GEMM_SMEM ((128*128 + GEMM_BM*128) * 4)
__global__ void k_gemm128(const float* __restrict__ Aext,
                          const float* __restrict__ W, int M, int relu) {
    extern __shared__ float sm[];
    float*  Ws  = sm;                 // 128*128
    float*  As  = sm + 128 * 128;     // BM*128
    float4* Ws4 = (float4*)Ws;
    float4* As4 = (float4*)As;

    const float* A = Aext ? Aext : g_agg;
    int tid = threadIdx.x;

    const float4* W4 = (const float4*)W;
    #pragma unroll
    for (int i = 0; i < 16; i++) Ws4[tid + i * 256] = W4[tid + i * 256];

    int row0 = blockIdx.x * GEMM_BM;
    const float4* A4 = (const float4*)A;
    #pragma unroll
    for (int i = 0; i < 8; i++) {
        int idx = tid + i * 256;       // 0..2047
        int r   = idx >> 5;
        float4 v = make_float4(0.f, 0.f, 0.f, 0.f);
        if (row0 + r < M) {
            v = A4[(size_t)(row0 + r) * 32 + (idx & 31)];
            if (relu) {
                v.x = fmaxf(v.x, 0.f); v.y = fmaxf(v.y, 0.f);
                v.z = fmaxf(v.z, 0.f); v.w = fmaxf(v.w, 0.f);
            }
        }
        As4[idx] = v;
    }
    __syncthreads();

    int warp = tid >> 5, lane = tid & 31;
    int rbase = warp * 8;

    float4 acc[8];
    #pragma unroll
    for (int r = 0; r < 8; r++) acc[r] = make_float4(0.f, 0.f, 0.f, 0.f);

    // k processed 4 at a time: A fetched as one float4 broadcast per row
    #pragma unroll 4
    for (int k4 = 0; k4 < 32; k4++) {
        float4 w0 = Ws4[(k4 * 4 + 0) * 32 + lane];
        float4 w1 = Ws4[(k4 * 4 + 1) * 32 + lane];
        float4 w2 = Ws4[(k4 * 4 + 2) * 32 + lane];
        float4 w3 = Ws4[(k4 * 4 + 3) * 32 + lane];
        #pragma unroll
        for (int r = 0; r < 8; r++) {
            float4 a = As4[(rbase + r) * 32 + k4];
            acc[r].x = fmaf(a.x, w0.x, acc[r].x); acc[r].y = fmaf(a.x, w0.y, acc[r].y);
            acc[r].z = fmaf(a.x, w0.z, acc[r].z); acc[r].w = fmaf(a.x, w0.w, acc[r].w);
            acc[r].x = fmaf(a.y, w1.x, acc[r].x); acc[r].y = fmaf(a.y, w1.y, acc[r].y);
            acc[r].z = fmaf(a.y, w1.z, acc[r].z); acc[r].w = fmaf(a.y, w1.w, acc[r].w);
            acc[r].x = fmaf(a.z, w2.x, acc[r].x); acc[r].y = fmaf(a.z, w2.y, acc[r].y);
            acc[r].z = fmaf(a.z, w2.z, acc[r].z); acc[r].w = fmaf(a.z, w2.w, acc[r].w);
            acc[r].x = fmaf(a.w, w3.x, acc[r].x); acc[r].y = fmaf(a.w, w3.y, acc[r].y);
            acc[r].z = fmaf(a.w, w3.z, acc[r].z); acc[r].w = fmaf(a.w, w3.w, acc[r].w);
        }
    }

    float4* O4 = (float4*)g_lin;
    #pragma unroll
    for (int r = 0; r < 8; r++) {
        int row = row0 + rbase + r;
        if (row < M) {
            float dv = g_dinv[row];
            float4 o;
            o.x = acc[r].x * dv; o.y = acc[r].y * dv;
            o.z = acc[r].z * dv; o.w = acc[r].w * dv;
            O4[(size_t)row * 32 + lane] = o;
        }
    }
}

// ---------------------------------------------------------------- aggregate: agg[d] = b + dinv[d]*(lin'[d] + sum lin'[s])
__global__ void k_aggregate(const float* __restrict__ b, int n) {
    int gwarp = (blockIdx.x * blockDim.x + threadIdx.x) >> 5;
    int lane  = threadIdx.x & 31;
    if (gwarp >= n) return;

    const float4* lin4 = (const float4*)g_lin;
    float4 acc = lin4[(size_t)gwarp * 32 + lane];   // self term (already dinv-scaled)

    int beg = g_rowptr[gwarp];
    int end = g_rowptr[gwarp + 1];
    for (int base = beg; base < end; base += 32) {
        int cnt = end - base; if (cnt > 32) cnt = 32;
        int sj = (base + lane < end) ? g_csrsrc[base + lane] : 0;
        #pragma unroll 8
        for (int t = 0; t < cnt; t++) {
            int s = __shfl_sync(0xffffffffu, sj, t);
            float4 v = lin4[(size_t)s * 32 + lane];
            acc.x += v.x; acc.y += v.y; acc.z += v.z; acc.w += v.w;
        }
    }

    float di = g_dinv[gwarp];
    float4 bb = ((const float4*)b)[lane];
    float4 o;
    o.x = fmaf(acc.x, di, bb.x);
    o.y = fmaf(acc.y, di, bb.y);
    o.z = fmaf(acc.z, di, bb.z);
    o.w = fmaf(acc.w, di, bb.w);
    ((float4*)g_agg)[(size_t)gwarp * 32 + lane] = o;
}

// ---------------------------------------------------------------- node projection as blocked GEMM:
// P[n, 32] = relu(g_agg[n,128]) @ Wp[128,32], Wp packed from Wfc rows 0..255.
#define PROJ_BM 64
__global__ void k_proj(const float* __restrict__ Wfc, int n) {
    __shared__ float Ws[128 * 32];        // Ws[k*32 + l]
    __shared__ float As[PROJ_BM * 128];   // 32 KB

    int tid = threadIdx.x;
    for (int idx = tid; idx < 128 * 32; idx += 256) {
        int k = idx >> 5, l = idx & 31;
        Ws[idx] = (l < 16) ? Wfc[k * 16 + l] : Wfc[(128 + k) * 16 + (l - 16)];
    }

    int row0 = blockIdx.x * PROJ_BM;
    float4* As4 = (float4*)As;
    const float4* A4 = (const float4*)g_agg;
    #pragma unroll
    for (int i = 0; i < 8; i++) {
        int idx = tid + i * 256;          // 0..2047
        int r   = idx >> 5;
        float4 v = make_float4(0.f, 0.f, 0.f, 0.f);
        if (row0 + r < n) {
            v = A4[(size_t)(row0 + r) * 32 + (idx & 31)];
            v.x = fmaxf(v.x, 0.f); v.y = fmaxf(v.y, 0.f);
            v.z = fmaxf(v.z, 0.f); v.w = fmaxf(v.w, 0.f);
        }
        As4[idx] = v;
    }
    __syncthreads();

    int warp = tid >> 5, lane = tid & 31;
    int rbase = warp * 8;

    float acc[8];
    #pragma unroll
    for (int r = 0; r < 8; r++) acc[r] = 0.f;

    #pragma unroll 4
    for (int k4 = 0; k4 < 32; k4++) {
        float w0 = Ws[(k4 * 4 + 0) * 32 + lane];
        float w1 = Ws[(k4 * 4 + 1) * 32 + lane];
        float w2 = Ws[(k4 * 4 + 2) * 32 + lane];
        float w3 = Ws[(k4 * 4 + 3) * 32 + lane];
        #pragma unroll
        for (int r = 0; r < 8; r++) {
            float4 a = As4[(rbase + r) * 32 + k4];
            acc[r] = fmaf(a.x, w0, acc[r]);
            acc[r] = fmaf(a.y, w1, acc[r]);
            acc[r] = fmaf(a.z, w2, acc[r]);
            acc[r] = fmaf(a.w, w3, acc[r]);
        }
    }

    #pragma unroll
    for (int r = 0; r < 8; r++) {
        int row = row0 + rbase + r;
        if (row < n) g_P[(size_t)row * 32 + lane] = acc[r];
    }
}

// ---------------------------------------------------------------- edge output: out = logsoftmax(P_src[s] + P_dst[d] + ea@We + b)
#define EB 16   // edges per block (256 threads = 16 edges x 16 classes)
__global__ void k_edge2(const int* __restrict__ src, const int* __restrict__ dst,
                        const float* __restrict__ eattr,
                        const float* __restrict__ Wfc, const float* __restrict__ bfc,
                        float* __restrict__ out, int e) {
    __shared__ float We[32 * 16];    // Wfc rows 256..287
    __shared__ float bs[CDIM];
    __shared__ float ea[EB][33];     // padded to kill bank conflicts

    int tid = threadIdx.x;
    for (int i = tid; i < 32 * 16; i += 256) We[i] = Wfc[256 * 16 + i];
    if (tid < CDIM) bs[tid] = bfc[tid];

    int e0 = blockIdx.x * EB;
    if (tid < 128) {
        int el = tid >> 3, q = tid & 7;
        if (e0 + el < e) {
            float4 v = ((const float4*)(eattr + (size_t)(e0 + el) * 32))[q];
            ea[el][q * 4 + 0] = v.x; ea[el][q * 4 + 1] = v.y;
            ea[el][q * 4 + 2] = v.z; ea[el][q * 4 + 3] = v.w;
        }
    }
    __syncthreads();

    int el = tid >> 4, c = tid & 15;
    int edge = e0 + el;
    bool valid = edge < e;
    int ce = valid ? edge : e - 1;

    int s = src[ce], d = dst[ce];
    float acc = bs[c] + g_P[(size_t)s * 32 + c] + g_P[(size_t)d * 32 + 16 + c];
    #pragma unroll
    for (int k = 0; k < 32; k++)
        acc = fmaf(ea[el][k], We[k * 16 + c], acc);

    float m = acc;
    #pragma unroll
    for (int off = 8; off; off >>= 1)
        m = fmaxf(m, __shfl_xor_sync(0xffffffffu, m, off));
    float ex = __expf(acc - m);
    float ss = ex;
    #pragma unroll
    for (int off = 8; off; off >>= 1)
        ss += __shfl_xor_sync(0xffffffffu, ss, off);
    float res = acc - m - __logf(ss);
    if (valid) out[(size_t)edge * CDIM + c] = res;
}

// ---------------------------------------------------------------- launch
extern "C" void kernel_launch(void* const* d_in, const int* in_sizes, int n_in,
                              void* d_out, int out_size) {
    const float* x     = (const float*)d_in[0];
    const int*   ei    = (const int*)  d_in[1];
    const float* eattr = (const float*)d_in[2];
    const float* W1 = (const float*)d_in[3];  const float* b1 = (const float*)d_in[4];
    const float* W2 = (const float*)d_in[5];  const float* b2 = (const float*)d_in[6];
    const float* W3 = (const float*)d_in[7];  const float* b3 = (const float*)d_in[8];
    const float* Wfc = (const float*)d_in[9]; const float* bfc = (const float*)d_in[10];
    float* out = (float*)d_out;

    int n = in_sizes[0] / HDIM;
    int e = in_sizes[1] / 2;
    const int* src = ei;
    const int* dst = ei + e;

    cudaFuncSetAttribute(k_gemm128, cudaFuncAttributeMaxDynamicSharedMemorySize, GEMM_SMEM);

    int bn   = (n + 255) / 256;
    int be   = (e + 255) / 256;
    int bgem = (n + GEMM_BM - 1) / GEMM_BM;
    int bagg = (n + 7) / 8;
    int bedg = (e + EB - 1) / EB;
    int nscan = (n + SCAN_B - 1) / SCAN_B;

    // ---- CSR build (once; reused by all 3 layers) + degree norm
    k_cnt_zero<<<bn, 256>>>(n);
    k_hist    <<<be, 256>>>(dst, e);
    k_scan1   <<<nscan, SCAN_B>>>(n);
    k_scan2   <<<1, 128>>>(nscan);
    k_scan3   <<<nscan, SCAN_B>>>(n, e);
    k_fill    <<<be, 256>>>(src, dst, e);

    // ---- 3 GCN layers (lin' pre-scaled by dinv in GEMM epilogue)
    k_gemm128  <<<bgem, 256, GEMM_SMEM>>>(x, W1, n, 0);
    k_aggregate<<<bagg, 256>>>(b1, n);

    k_gemm128  <<<bgem, 256, GEMM_SMEM>>>(nullptr, W2, n, 1);
    k_aggregate<<<bagg, 256>>>(b2, n);

    k_gemm128  <<<bgem, 256, GEMM_SMEM>>>(nullptr, W3, n, 1);
    k_aggregate<<<bagg, 256>>>(b3, n);

    // ---- factored edge classifier
    k_proj <<<(n + PROJ_BM - 1) / PROJ_BM, 256>>>(Wfc, n);
    k_edge2<<<bedg, 256>>>(src, dst, eattr, Wfc, bfc, out, e);
}